// round 6
// baseline (speedup 1.0000x reference)
#include <cuda_runtime.h>
#include <cstdint>

#define NB 64
#define SL 510
#define SLP 532          // padded step stride (prefetch overrun room)
#define NT 9
#define HID 768
#define FULLM 0xffffffffu

// Scratch (no dynamic allocation allowed). Zero-initialized at load.
__device__ float g_emiss[NB * SLP * NT];
__device__ float g_den[NB];

// ---------------------------------------------------------------------------
// Kernel A: emissions[b, s, t] = dot(hidden[b, s+1, :], weight[t, :]) + bias[t]
// 2 rows per warp, 16-lane K-split: lanes 0-15 -> row r0, lanes 16-31 -> row
// r0+1, both halves read IDENTICAL weight smem addresses (broadcast dedup ->
// crossbar traffic halved vs 1-row/warp). Each lane owns 12 float4 of its row.
// SL=510 is even, so row pairs never straddle batches.
// ---------------------------------------------------------------------------
__global__ __launch_bounds__(256) void emis_kernel(
    const float* __restrict__ hidden,
    const float* __restrict__ weight,
    const float* __restrict__ bias) {
    __shared__ float4 ws4[NT * 192];        // 27,648 B
    __shared__ float bs[NT];

    int tid = threadIdx.x;
    for (int i = tid; i < NT * 192; i += 256)
        ws4[i] = ((const float4*)weight)[i];
    if (tid < NT) bs[tid] = bias[tid];
    __syncthreads();

    int lane = tid & 31;
    int half = lane >> 4;
    int sub = lane & 15;
    int w = blockIdx.x * 8 + (tid >> 5);    // warp id 0..16319
    int r = w * 2 + half;                   // global row
    int b = r / SL;
    int s = r - b * SL;

    const float4* hp =
        (const float4*)(hidden + (size_t)(b * 512 + s + 1) * HID) + sub;

    float4 h[12];
#pragma unroll
    for (int u = 0; u < 12; u++) h[u] = hp[u * 16];

    float acc[NT];
#pragma unroll
    for (int t = 0; t < NT; t++) acc[t] = 0.f;

#pragma unroll
    for (int u = 0; u < 12; u++) {
#pragma unroll
        for (int t = 0; t < NT; t++) {
            float4 wv = ws4[t * 192 + u * 16 + sub];   // same addr both halves
            acc[t] = fmaf(h[u].x, wv.x, fmaf(h[u].y, wv.y,
                     fmaf(h[u].z, wv.z, fmaf(h[u].w, wv.w, acc[t]))));
        }
    }

    // reduce within each 16-lane half (xor offsets < 16 stay in-half)
#pragma unroll
    for (int t = 0; t < NT; t++) {
#pragma unroll
        for (int off = 8; off > 0; off >>= 1)
            acc[t] += __shfl_xor_sync(FULLM, acc[t], off);
    }

    if (sub < NT)
        g_emiss[((size_t)b * SLP + s) * NT + sub] = acc[sub] + bs[sub];
}

// ---------------------------------------------------------------------------
// Kernel B: per-batch CRF, 1 warp per block, 2 blocks per batch:
//   role 0: linear-domain forward (denominator only; power-2 rescale / 8)
//   role 1: Viterbi max-plus forward + history + parallel backtrack
// Emissions staged once into smem; per-step access = depth-4 LDS ring.
// ---------------------------------------------------------------------------
__global__ __launch_bounds__(32) void crf_kernel(
    const int* __restrict__ labels,
    const float* __restrict__ start_t,
    const float* __restrict__ end_t,
    const float* __restrict__ trans,
    float* __restrict__ out) {
    __shared__ float s_em[SLP * NT];            // 19,152 B
    __shared__ int s_lbl[528];
    __shared__ unsigned char hist[512 * 12];    // role 1 only

    int blk = blockIdx.x;
    int b = blk >> 1;
    int role = blk & 1;
    int lane = threadIdx.x;
    bool act = lane < NT;
    int lj = act ? lane : 0;

    const int* lbl = labels + b * 512;

    // stage labels
    for (int i = lane; i < 512; i += 32) s_lbl[i] = lbl[i];
    __syncwarp();
    if (lane < 17) s_lbl[511 + lane] = -1;      // window excludes index 511+

    // stage emissions (SLP*NT = 4788 floats = 1197 float4)
    const float4* g4 = (const float4*)(g_emiss + (size_t)b * SLP * NT);
    float4* se4 = (float4*)s_em;
    for (int i = lane; i < (SLP * NT) / 4; i += 32) se4[i] = g4[i];
    __syncwarp();

    if (role == 0) {
        // ============== ALPHA (linear domain, power-2 rescaled) ============
        float texp[NT];
#pragma unroll
        for (int i = 0; i < NT; i++) texp[i] = __expf(trans[i * NT + lj]);

        float em0 = act ? s_em[lane] : -1e30f;
        float alpha = act ? __expf(start_t[lane] + em0) : 0.f;
        int acc_e = 0;

        // depth-4 exp ring (LDS 29 + MUFU 16 << 4 steps of work)
        float pe_r[4];
#pragma unroll
        for (int u = 0; u < 4; u++)
            pe_r[u] = __expf(act ? s_em[(1 + u) * NT + lane] : -1e30f);

        for (int g = 0; g < 64; ++g) {
            int sbase = 1 + (g << 3);
#pragma unroll
            for (int u = 0; u < 8; u++) {
                int s = sbase + u;
                float pe_c = pe_r[u & 3];
                float nem = act ? s_em[(s + 4) * NT + lane] : -1e30f;
                pe_r[u & 3] = __expf(nem);

                int m = s_lbl[s + 1] >= 0;

                float b0 = __shfl_sync(FULLM, alpha, 0);
                float b1 = __shfl_sync(FULLM, alpha, 1);
                float b2 = __shfl_sync(FULLM, alpha, 2);
                float b3 = __shfl_sync(FULLM, alpha, 3);
                float b4 = __shfl_sync(FULLM, alpha, 4);
                float b5 = __shfl_sync(FULLM, alpha, 5);
                float b6 = __shfl_sync(FULLM, alpha, 6);
                float b7 = __shfl_sync(FULLM, alpha, 7);
                float b8 = __shfl_sync(FULLM, alpha, 8);

                float d0 = fmaf(b6, texp[6], fmaf(b3, texp[3], b0 * texp[0]));
                float d1 = fmaf(b7, texp[7], fmaf(b4, texp[4], b1 * texp[1]));
                float d2 = fmaf(b8, texp[8], fmaf(b5, texp[5], b2 * texp[2]));
                float an = ((d0 + d1) + d2) * pe_c;
                alpha = m ? an : alpha;
            }
            // exact power-of-2 rescale once per 8 steps
            float ref = __shfl_sync(FULLM, alpha, 4);
            int Eb = (__float_as_int(ref) >> 23) & 0xff;
            int Es = Eb ? Eb : 127;
            alpha *= __int_as_float((254 - Es) << 23);
            acc_e += Es - 127;
        }

        float fa = act ? alpha * __expf(end_t[lane]) : 0.f;
        fa += __shfl_xor_sync(FULLM, fa, 8);
        fa += __shfl_xor_sync(FULLM, fa, 4);
        fa += __shfl_xor_sync(FULLM, fa, 2);
        fa += __shfl_xor_sync(FULLM, fa, 1);
        float den = __logf(fa) + (float)acc_e * 0.69314718056f;

        if (lane == 0) g_den[b] = den;
    } else {
        // ================= VITERBI + HISTORY + PARALLEL BACKTRACK ==========
        float tr[NT];
#pragma unroll
        for (int i = 0; i < NT; i++) tr[i] = trans[i * NT + lj];
        float endv = act ? end_t[lane] : -1e30f;

        float vs = act ? (start_t[lane] + s_em[lane]) : -1e30f;

        float em_r[4];
#pragma unroll
        for (int u = 0; u < 4; u++)
            em_r[u] = act ? s_em[(1 + u) * NT + lane] : 0.f;

        for (int g = 0; g < 64; ++g) {
            int sbase = 1 + (g << 3);
#pragma unroll
            for (int u = 0; u < 8; u++) {
                int s = sbase + u;
                float em_c = em_r[u & 3];
                em_r[u & 3] = act ? s_em[(s + 4) * NT + lane] : 0.f;

                int m = s_lbl[s + 1] >= 0;

                float x0 = __shfl_sync(FULLM, vs, 0) + tr[0];
                float x1 = __shfl_sync(FULLM, vs, 1) + tr[1];
                float x2 = __shfl_sync(FULLM, vs, 2) + tr[2];
                float x3 = __shfl_sync(FULLM, vs, 3) + tr[3];
                float x4 = __shfl_sync(FULLM, vs, 4) + tr[4];
                float x5 = __shfl_sync(FULLM, vs, 5) + tr[5];
                float x6 = __shfl_sync(FULLM, vs, 6) + tr[6];
                float x7 = __shfl_sync(FULLM, vs, 7) + tr[7];
                float x8 = __shfl_sync(FULLM, vs, 8) + tr[8];

                // value via fmax tree (exact, order-free); +em AFTER max
                // (matches reference association exactly)
                float mA = fmaxf(fmaxf(fmaxf(x0, x1), fmaxf(x2, x3)),
                                 fmaxf(fmaxf(x4, x5), fmaxf(x6, fmaxf(x7, x8))));
                float vn = mA + em_c;
                vs = (m && act) ? vn : vs;

                // first-index argmax (off critical path)
                int bi = 8;
                if (x7 == mA) bi = 7;
                if (x6 == mA) bi = 6;
                if (x5 == mA) bi = 5;
                if (x4 == mA) bi = 4;
                if (x3 == mA) bi = 3;
                if (x2 == mA) bi = 2;
                if (x1 == mA) bi = 1;
                if (x0 == mA) bi = 0;

                if (act)
                    hist[(s - 1) * 12 + lane] = (unsigned char)(m ? bi : lane);
            }
        }

        // final tag: argmax over 9 with first-index tie-break (16-lane bfly)
        float fv = vs + endv;
        int fi = act ? lane : 15;
#pragma unroll
        for (int off = 8; off > 0; off >>= 1) {
            float ov = __shfl_xor_sync(FULLM, fv, off);
            int oi = __shfl_xor_sync(FULLM, fi, off);
            bool take = (ov > fv) || (ov == fv && oi < fi);
            fv = take ? ov : fv;
            fi = take ? oi : fi;
        }
        int last = __shfl_sync(FULLM, fi, 0);
        __syncwarp();

        // ---- parallel backtrack: 16-step segment maps, nibble-packed ----
        int a = lane * 16;
        int bnd = a + 16 < (SL - 1) ? a + 16 : (SL - 1);   // clamp to 509
        unsigned long long F = 0x876543210ull;             // identity map
        for (int s = bnd - 1; s >= a; --s) {
            const unsigned char* hr = hist + s * 12;
            unsigned long long nF = 0;
#pragma unroll
            for (int t = 0; t < NT; t++) {
                int e = (int)((F >> (4 * t)) & 15);
                nF |= ((unsigned long long)hr[e]) << (4 * t);
            }
            F = nF;
        }

        unsigned int flo = (unsigned int)F;
        unsigned int fhi = (unsigned int)(F >> 32);
        int cur = last;
        int my_entry = (lane == 31) ? last : 0;
        for (int l = 31; l >= 1; --l) {
            unsigned int lo = __shfl_sync(FULLM, flo, l);
            unsigned int hi = __shfl_sync(FULLM, fhi, l);
            unsigned long long Fl = ((unsigned long long)hi << 32) | lo;
            cur = (int)((Fl >> (4 * cur)) & 15);
            if (lane == l - 1) my_entry = cur;
        }

        float* otag = out + 1 + (size_t)b * SL;
        if (lane == 31) {
            otag[SL - 1] = (s_lbl[SL] >= 0) ? (float)last : 0.f;
        }
        int c2 = my_entry;
        for (int s = bnd - 1; s >= a; --s) {
            c2 = hist[s * 12 + c2];
            otag[s] = (s_lbl[s + 1] >= 0) ? (float)c2 : 0.f;
        }
    }
}

// ---------------------------------------------------------------------------
// Kernel C: parallel numerator (per batch) + final reduce.
// 1 block x 1024 threads = 32 warps; warp w handles batches w and w+32.
// Numerator is a plain sum -> order-free, parallelized 16 steps/lane with a
// mask-aware last-valid-tag scan for cross-segment transition terms.
// ---------------------------------------------------------------------------
__global__ __launch_bounds__(1024) void numer_reduce_kernel(
    const int* __restrict__ labels,
    const float* __restrict__ start_t,
    const float* __restrict__ end_t,
    const float* __restrict__ trans,
    float* __restrict__ out) {
    __shared__ float s_tr[NT * NT];
    __shared__ float part[NB];

    int tid = threadIdx.x;
    int wid = tid >> 5;
    int lane = tid & 31;
    if (tid < NT * NT) s_tr[tid] = trans[tid];
    __syncthreads();

    for (int bb = wid; bb < NB; bb += 32) {
        const int* lbl = labels + bb * 512;
        const float* em = g_emiss + (size_t)bb * SLP * NT;

        int t0 = lane * 16;
        float sum = 0.f;
        int prev = -1;      // local prev within segment (-1 = none yet)
        int ftag = -1;      // first valid tag in segment

        for (int k = 0; k < 16; ++k) {
            int t = t0 + k;
            if (t == 0 || t > 509) continue;
            int lv = lbl[t + 1];
            if (lv >= 0) {
                sum += em[t * NT + lv];
                if (prev >= 0) sum += s_tr[prev * NT + lv];
                else ftag = lv;
                prev = lv;
            }
        }

        int l1 = lbl[1];
        int tag0 = (l1 >= 0) ? l1 : 0;

        // inclusive scan of last-valid-tag (op: b<0 ? a : b)
        int x = prev;
#pragma unroll
        for (int off = 1; off < 32; off <<= 1) {
            int y = __shfl_up_sync(FULLM, x, off);
            if (lane >= off && x < 0) x = y;
        }
        int excl = __shfl_up_sync(FULLM, x, 1);
        int carry = (lane == 0 || excl < 0) ? tag0 : excl;

        if (ftag >= 0) sum += s_tr[carry * NT + ftag];
        if (lane == 0) sum += start_t[tag0] + em[tag0];   // t=0 base term
        if (lane == 31) {
            int lastt = (x < 0) ? tag0 : x;
            sum += end_t[lastt];
        }

#pragma unroll
        for (int off = 16; off > 0; off >>= 1)
            sum += __shfl_xor_sync(FULLM, sum, off);
        if (lane == 0) part[bb] = sum - g_den[bb];        // numer - den
    }
    __syncthreads();

    if (tid < 32) {
        float v = part[tid] + part[tid + 32];
#pragma unroll
        for (int off = 16; off > 0; off >>= 1)
            v += __shfl_xor_sync(FULLM, v, off);
        if (tid == 0) out[0] = -v;
    }
}

// ---------------------------------------------------------------------------
extern "C" void kernel_launch(void* const* d_in, const int* in_sizes, int n_in,
                              void* d_out, int out_size) {
    const float* hidden  = (const float*)d_in[0];
    const int*   labels  = (const int*)d_in[1];
    const float* weight  = (const float*)d_in[2];
    const float* bias    = (const float*)d_in[3];
    const float* start_t = (const float*)d_in[4];
    const float* end_t   = (const float*)d_in[5];
    const float* trans   = (const float*)d_in[6];
    float* out = (float*)d_out;

    emis_kernel<<<2040, 256>>>(hidden, weight, bias);
    crf_kernel<<<2 * NB, 32>>>(labels, start_t, end_t, trans, out);
    numer_reduce_kernel<<<1, 1024>>>(labels, start_t, end_t, trans, out);
}

// round 7
// speedup vs baseline: 1.0150x; 1.0150x over previous
#include <cuda_runtime.h>
#include <cstdint>

#define NB 64
#define SL 510
#define SLP 532          // padded step stride (prefetch overrun room)
#define NT 9
#define HID 768
#define FULLM 0xffffffffu

// Scratch (no dynamic allocation allowed). Zero-initialized at load.
__device__ float g_emiss[NB * SLP * NT];
__device__ float g_den[NB];

// ---------------------------------------------------------------------------
// Kernel A: emissions[b, s, t] = dot(hidden[b, s+1, :], weight[t, :]) + bias[t]
// 2 rows per warp, 16-lane K-split: lanes 0-15 -> row r0, lanes 16-31 -> row
// r0+1, both halves read IDENTICAL weight smem addresses (broadcast dedup ->
// crossbar traffic halved vs 1-row/warp). Each lane owns 12 float4 of its row.
// SL=510 is even, so row pairs never straddle batches.
// ---------------------------------------------------------------------------
__global__ __launch_bounds__(256) void emis_kernel(
    const float* __restrict__ hidden,
    const float* __restrict__ weight,
    const float* __restrict__ bias) {
    __shared__ float4 ws4[NT * 192];        // 27,648 B
    __shared__ float bs[NT];

    int tid = threadIdx.x;
    for (int i = tid; i < NT * 192; i += 256)
        ws4[i] = ((const float4*)weight)[i];
    if (tid < NT) bs[tid] = bias[tid];
    __syncthreads();

    int lane = tid & 31;
    int half = lane >> 4;
    int sub = lane & 15;
    int w = blockIdx.x * 8 + (tid >> 5);    // warp id 0..16319
    int r = w * 2 + half;                   // global row
    int b = r / SL;
    int s = r - b * SL;

    const float4* hp =
        (const float4*)(hidden + (size_t)(b * 512 + s + 1) * HID) + sub;

    float4 h[12];
#pragma unroll
    for (int u = 0; u < 12; u++) h[u] = hp[u * 16];

    float acc[NT];
#pragma unroll
    for (int t = 0; t < NT; t++) acc[t] = 0.f;

#pragma unroll
    for (int u = 0; u < 12; u++) {
#pragma unroll
        for (int t = 0; t < NT; t++) {
            float4 wv = ws4[t * 192 + u * 16 + sub];   // same addr both halves
            acc[t] = fmaf(h[u].x, wv.x, fmaf(h[u].y, wv.y,
                     fmaf(h[u].z, wv.z, fmaf(h[u].w, wv.w, acc[t]))));
        }
    }

    // reduce within each 16-lane half (xor offsets < 16 stay in-half)
#pragma unroll
    for (int t = 0; t < NT; t++) {
#pragma unroll
        for (int off = 8; off > 0; off >>= 1)
            acc[t] += __shfl_xor_sync(FULLM, acc[t], off);
    }

    if (sub < NT)
        g_emiss[((size_t)b * SLP + s) * NT + sub] = acc[sub] + bs[sub];
}

// ---------------------------------------------------------------------------
// Kernel B: per-batch CRF, 1 warp per block, 2 blocks per batch:
//   role 0: linear-domain forward (denominator only; power-2 rescale / 8)
//   role 1: Viterbi max-plus forward + history + parallel backtrack
// Emissions staged once into smem; per-step access = depth-4 LDS ring.
// ---------------------------------------------------------------------------
__global__ __launch_bounds__(32) void crf_kernel(
    const int* __restrict__ labels,
    const float* __restrict__ start_t,
    const float* __restrict__ end_t,
    const float* __restrict__ trans,
    float* __restrict__ out) {
    __shared__ float s_em[SLP * NT];            // 19,152 B
    __shared__ int s_lbl[528];
    __shared__ unsigned char hist[512 * 12];    // role 1 only

    int blk = blockIdx.x;
    int b = blk >> 1;
    int role = blk & 1;
    int lane = threadIdx.x;
    bool act = lane < NT;
    int lj = act ? lane : 0;

    const int* lbl = labels + b * 512;

    // stage labels
    for (int i = lane; i < 512; i += 32) s_lbl[i] = lbl[i];
    __syncwarp();
    if (lane < 17) s_lbl[511 + lane] = -1;      // window excludes index 511+

    // stage emissions (SLP*NT = 4788 floats = 1197 float4)
    const float4* g4 = (const float4*)(g_emiss + (size_t)b * SLP * NT);
    float4* se4 = (float4*)s_em;
    for (int i = lane; i < (SLP * NT) / 4; i += 32) se4[i] = g4[i];
    __syncwarp();

    if (role == 0) {
        // ============== ALPHA (linear domain, power-2 rescaled) ============
        float texp[NT];
#pragma unroll
        for (int i = 0; i < NT; i++) texp[i] = __expf(trans[i * NT + lj]);

        float em0 = act ? s_em[lane] : -1e30f;
        float alpha = act ? __expf(start_t[lane] + em0) : 0.f;
        int acc_e = 0;

        // depth-4 exp ring (LDS 29 + MUFU 16 << 4 steps of work)
        float pe_r[4];
#pragma unroll
        for (int u = 0; u < 4; u++)
            pe_r[u] = __expf(act ? s_em[(1 + u) * NT + lane] : -1e30f);

        for (int g = 0; g < 64; ++g) {
            int sbase = 1 + (g << 3);
#pragma unroll
            for (int u = 0; u < 8; u++) {
                int s = sbase + u;
                float pe_c = pe_r[u & 3];
                float nem = act ? s_em[(s + 4) * NT + lane] : -1e30f;
                pe_r[u & 3] = __expf(nem);

                int m = s_lbl[s + 1] >= 0;

                float b0 = __shfl_sync(FULLM, alpha, 0);
                float b1 = __shfl_sync(FULLM, alpha, 1);
                float b2 = __shfl_sync(FULLM, alpha, 2);
                float b3 = __shfl_sync(FULLM, alpha, 3);
                float b4 = __shfl_sync(FULLM, alpha, 4);
                float b5 = __shfl_sync(FULLM, alpha, 5);
                float b6 = __shfl_sync(FULLM, alpha, 6);
                float b7 = __shfl_sync(FULLM, alpha, 7);
                float b8 = __shfl_sync(FULLM, alpha, 8);

                float d0 = fmaf(b6, texp[6], fmaf(b3, texp[3], b0 * texp[0]));
                float d1 = fmaf(b7, texp[7], fmaf(b4, texp[4], b1 * texp[1]));
                float d2 = fmaf(b8, texp[8], fmaf(b5, texp[5], b2 * texp[2]));
                float an = ((d0 + d1) + d2) * pe_c;
                alpha = m ? an : alpha;
            }
            // exact power-of-2 rescale once per 8 steps
            float ref = __shfl_sync(FULLM, alpha, 4);
            int Eb = (__float_as_int(ref) >> 23) & 0xff;
            int Es = Eb ? Eb : 127;
            alpha *= __int_as_float((254 - Es) << 23);
            acc_e += Es - 127;
        }

        float fa = act ? alpha * __expf(end_t[lane]) : 0.f;
        fa += __shfl_xor_sync(FULLM, fa, 8);
        fa += __shfl_xor_sync(FULLM, fa, 4);
        fa += __shfl_xor_sync(FULLM, fa, 2);
        fa += __shfl_xor_sync(FULLM, fa, 1);
        float den = __logf(fa) + (float)acc_e * 0.69314718056f;

        if (lane == 0) g_den[b] = den;
    } else {
        // ================= VITERBI + HISTORY + PARALLEL BACKTRACK ==========
        float tr[NT];
#pragma unroll
        for (int i = 0; i < NT; i++) tr[i] = trans[i * NT + lj];
        float endv = act ? end_t[lane] : -1e30f;

        float vs = act ? (start_t[lane] + s_em[lane]) : -1e30f;

        float em_r[4];
#pragma unroll
        for (int u = 0; u < 4; u++)
            em_r[u] = act ? s_em[(1 + u) * NT + lane] : 0.f;

        for (int g = 0; g < 64; ++g) {
            int sbase = 1 + (g << 3);
#pragma unroll
            for (int u = 0; u < 8; u++) {
                int s = sbase + u;
                float em_c = em_r[u & 3];
                em_r[u & 3] = act ? s_em[(s + 4) * NT + lane] : 0.f;

                int m = s_lbl[s + 1] >= 0;

                float x0 = __shfl_sync(FULLM, vs, 0) + tr[0];
                float x1 = __shfl_sync(FULLM, vs, 1) + tr[1];
                float x2 = __shfl_sync(FULLM, vs, 2) + tr[2];
                float x3 = __shfl_sync(FULLM, vs, 3) + tr[3];
                float x4 = __shfl_sync(FULLM, vs, 4) + tr[4];
                float x5 = __shfl_sync(FULLM, vs, 5) + tr[5];
                float x6 = __shfl_sync(FULLM, vs, 6) + tr[6];
                float x7 = __shfl_sync(FULLM, vs, 7) + tr[7];
                float x8 = __shfl_sync(FULLM, vs, 8) + tr[8];

                // value via fmax tree (exact, order-free); +em AFTER max
                // (matches reference association exactly)
                float mA = fmaxf(fmaxf(fmaxf(x0, x1), fmaxf(x2, x3)),
                                 fmaxf(fmaxf(x4, x5), fmaxf(x6, fmaxf(x7, x8))));
                float vn = mA + em_c;
                vs = (m && act) ? vn : vs;

                // first-index argmax (off critical path)
                int bi = 8;
                if (x7 == mA) bi = 7;
                if (x6 == mA) bi = 6;
                if (x5 == mA) bi = 5;
                if (x4 == mA) bi = 4;
                if (x3 == mA) bi = 3;
                if (x2 == mA) bi = 2;
                if (x1 == mA) bi = 1;
                if (x0 == mA) bi = 0;

                if (act)
                    hist[(s - 1) * 12 + lane] = (unsigned char)(m ? bi : lane);
            }
        }

        // final tag: argmax over 9 with first-index tie-break (16-lane bfly)
        float fv = vs + endv;
        int fi = act ? lane : 15;
#pragma unroll
        for (int off = 8; off > 0; off >>= 1) {
            float ov = __shfl_xor_sync(FULLM, fv, off);
            int oi = __shfl_xor_sync(FULLM, fi, off);
            bool take = (ov > fv) || (ov == fv && oi < fi);
            fv = take ? ov : fv;
            fi = take ? oi : fi;
        }
        int last = __shfl_sync(FULLM, fi, 0);
        __syncwarp();

        // ---- parallel backtrack: 16-step segment maps, nibble-packed ----
        int a = lane * 16;
        int bnd = a + 16 < (SL - 1) ? a + 16 : (SL - 1);   // clamp to 509
        unsigned long long F = 0x876543210ull;             // identity map
        for (int s = bnd - 1; s >= a; --s) {
            const unsigned char* hr = hist + s * 12;
            unsigned long long nF = 0;
#pragma unroll
            for (int t = 0; t < NT; t++) {
                int e = (int)((F >> (4 * t)) & 15);
                nF |= ((unsigned long long)hr[e]) << (4 * t);
            }
            F = nF;
        }

        unsigned int flo = (unsigned int)F;
        unsigned int fhi = (unsigned int)(F >> 32);
        int cur = last;
        int my_entry = (lane == 31) ? last : 0;
        for (int l = 31; l >= 1; --l) {
            unsigned int lo = __shfl_sync(FULLM, flo, l);
            unsigned int hi = __shfl_sync(FULLM, fhi, l);
            unsigned long long Fl = ((unsigned long long)hi << 32) | lo;
            cur = (int)((Fl >> (4 * cur)) & 15);
            if (lane == l - 1) my_entry = cur;
        }

        float* otag = out + 1 + (size_t)b * SL;
        if (lane == 31) {
            otag[SL - 1] = (s_lbl[SL] >= 0) ? (float)last : 0.f;
        }
        int c2 = my_entry;
        for (int s = bnd - 1; s >= a; --s) {
            c2 = hist[s * 12 + c2];
            otag[s] = (s_lbl[s + 1] >= 0) ? (float)c2 : 0.f;
        }
    }
}

// ---------------------------------------------------------------------------
// Kernel C: parallel numerator (per batch) + final reduce.
// 1 block x 1024 threads = 32 warps; warp w handles batches w and w+32.
// Numerator is a plain sum -> order-free, parallelized 16 steps/lane with a
// mask-aware last-valid-tag scan for cross-segment transition terms.
// ---------------------------------------------------------------------------
__global__ __launch_bounds__(1024) void numer_reduce_kernel(
    const int* __restrict__ labels,
    const float* __restrict__ start_t,
    const float* __restrict__ end_t,
    const float* __restrict__ trans,
    float* __restrict__ out) {
    __shared__ float s_tr[NT * NT];
    __shared__ float part[NB];

    int tid = threadIdx.x;
    int wid = tid >> 5;
    int lane = tid & 31;
    if (tid < NT * NT) s_tr[tid] = trans[tid];
    __syncthreads();

    for (int bb = wid; bb < NB; bb += 32) {
        const int* lbl = labels + bb * 512;
        const float* em = g_emiss + (size_t)bb * SLP * NT;

        int t0 = lane * 16;
        float sum = 0.f;
        int prev = -1;      // local prev within segment (-1 = none yet)
        int ftag = -1;      // first valid tag in segment

        for (int k = 0; k < 16; ++k) {
            int t = t0 + k;
            if (t == 0 || t > 509) continue;
            int lv = lbl[t + 1];
            if (lv >= 0) {
                sum += em[t * NT + lv];
                if (prev >= 0) sum += s_tr[prev * NT + lv];
                else ftag = lv;
                prev = lv;
            }
        }

        int l1 = lbl[1];
        int tag0 = (l1 >= 0) ? l1 : 0;

        // inclusive scan of last-valid-tag (op: b<0 ? a : b)
        int x = prev;
#pragma unroll
        for (int off = 1; off < 32; off <<= 1) {
            int y = __shfl_up_sync(FULLM, x, off);
            if (lane >= off && x < 0) x = y;
        }
        int excl = __shfl_up_sync(FULLM, x, 1);
        int carry = (lane == 0 || excl < 0) ? tag0 : excl;

        if (ftag >= 0) sum += s_tr[carry * NT + ftag];
        if (lane == 0) sum += start_t[tag0] + em[tag0];   // t=0 base term
        if (lane == 31) {
            int lastt = (x < 0) ? tag0 : x;
            sum += end_t[lastt];
        }

#pragma unroll
        for (int off = 16; off > 0; off >>= 1)
            sum += __shfl_xor_sync(FULLM, sum, off);
        if (lane == 0) part[bb] = sum - g_den[bb];        // numer - den
    }
    __syncthreads();

    if (tid < 32) {
        float v = part[tid] + part[tid + 32];
#pragma unroll
        for (int off = 16; off > 0; off >>= 1)
            v += __shfl_xor_sync(FULLM, v, off);
        if (tid == 0) out[0] = -v;
    }
}

// ---------------------------------------------------------------------------
extern "C" void kernel_launch(void* const* d_in, const int* in_sizes, int n_in,
                              void* d_out, int out_size) {
    const float* hidden  = (const float*)d_in[0];
    const int*   labels  = (const int*)d_in[1];
    const float* weight  = (const float*)d_in[2];
    const float* bias    = (const float*)d_in[3];
    const float* start_t = (const float*)d_in[4];
    const float* end_t   = (const float*)d_in[5];
    const float* trans   = (const float*)d_in[6];
    float* out = (float*)d_out;

    emis_kernel<<<2040, 256>>>(hidden, weight, bias);
    crf_kernel<<<2 * NB, 32>>>(labels, start_t, end_t, trans, out);
    numer_reduce_kernel<<<1, 1024>>>(labels, start_t, end_t, trans, out);
}

// round 8
// speedup vs baseline: 1.3825x; 1.3621x over previous
#include <cuda_runtime.h>
#include <cstdint>

#define NB 64
#define SL 510
#define SLP 532
#define NT 9
#define HID 768
#define FULLM 0xffffffffu

__device__ float g_emiss[NB * SLP * NT];   // zero-init; pad rows stay 0
__device__ float g_den[NB];
__device__ float g_part[NB];

__device__ __forceinline__ void fma2(unsigned long long& d,
                                     unsigned long long a,
                                     unsigned long long b) {
    asm("fma.rn.f32x2 %0, %1, %2, %3;" : "=l"(d) : "l"(a), "l"(b), "l"(d));
}
__device__ __forceinline__ float lo32(unsigned long long a) {
    return __uint_as_float((unsigned)a);
}
__device__ __forceinline__ float hi32(unsigned long long a) {
    return __uint_as_float((unsigned)(a >> 32));
}

// ---------------------------------------------------------------------------
// Kernel A: emissions. 4 rows/warp (quarter q=lane>>3), 8-lane K-split.
// All 4 quarters read identical weight smem addresses (broadcast dedup).
// Packed f32x2 FMA halves FFMA instruction count.
// ---------------------------------------------------------------------------
__global__ __launch_bounds__(256) void emis_kernel(
    const float* __restrict__ hidden,
    const float* __restrict__ weight,
    const float* __restrict__ bias) {
    __shared__ ulonglong2 ws2[NT * 192];    // 27,648 B
    __shared__ float bs[NT];

    int tid = threadIdx.x;
    for (int i = tid; i < NT * 192; i += 256)
        ws2[i] = ((const ulonglong2*)weight)[i];
    if (tid < NT) bs[tid] = bias[tid];
    __syncthreads();

    int lane = tid & 31;
    int q = lane >> 3;
    int sub = lane & 7;
    int w = blockIdx.x * 8 + (tid >> 5);
    int r = w * 4 + q;
    int b = r / SL;
    int s = r - b * SL;

    const ulonglong2* hp =
        (const ulonglong2*)(hidden + (size_t)(b * 512 + s + 1) * HID);

    unsigned long long acc2[NT];
#pragma unroll
    for (int t = 0; t < NT; t++) acc2[t] = 0ull;

#pragma unroll
    for (int p = 0; p < 2; p++) {
        ulonglong2 h[12];
#pragma unroll
        for (int u = 0; u < 12; u++) h[u] = hp[p * 96 + u * 8 + sub];
#pragma unroll
        for (int u = 0; u < 12; u++) {
#pragma unroll
            for (int t = 0; t < NT; t++) {
                ulonglong2 wv = ws2[t * 192 + p * 96 + u * 8 + sub];
                fma2(acc2[t], h[u].x, wv.x);
                fma2(acc2[t], h[u].y, wv.y);
            }
        }
    }

    float acc[NT];
#pragma unroll
    for (int t = 0; t < NT; t++) acc[t] = lo32(acc2[t]) + hi32(acc2[t]);
#pragma unroll
    for (int t = 0; t < NT; t++) {
#pragma unroll
        for (int off = 4; off > 0; off >>= 1)
            acc[t] += __shfl_xor_sync(FULLM, acc[t], off);
    }

    float* o = g_emiss + ((size_t)b * SLP + s) * NT;
#pragma unroll
    for (int t = 0; t < NT; t++) {
        int wsub = (t == 8) ? 0 : t;
        if (sub == wsub) o[t] = acc[t] + bs[t];
    }
}

// ---------------------------------------------------------------------------
// Kernel B: CRF. 192 blocks x 1 warp; blk = 3*b + role.
//  role 0: bidirectional denominator (lanes 0-8 forward, 16-24 backward)
//  role 1: Viterbi forward + history + parallel backtrack (bitwise-exact)
//  role 2: numerator (parallel scan, order-free sum)
// ---------------------------------------------------------------------------
__global__ __launch_bounds__(32) void crf_kernel(
    const int* __restrict__ labels,
    const float* __restrict__ start_t,
    const float* __restrict__ end_t,
    const float* __restrict__ trans,
    float* __restrict__ out) {
    __shared__ int s_lbl[528];
    __shared__ unsigned char hist[512 * 12];

    int blk = blockIdx.x;
    int b = blk / 3;
    int role = blk - 3 * b;
    int lane = threadIdx.x;
    bool act = lane < NT;
    int lj = act ? lane : 0;

    const float* em_base = g_emiss + (size_t)b * SLP * NT;
    const int* lbl = labels + b * 512;

    for (int i = lane; i < 512; i += 32) s_lbl[i] = lbl[i];
    __syncwarp();
    if (lane < 17) s_lbl[511 + lane] = -1;
    __syncwarp();

    if (role == 0) {
        // ===== bidirectional denominator, linear domain, pw2 rescale ======
        bool bwd = lane >= 16;
        int rowi = bwd ? ((lane - 16 < NT) ? lane - 16 : 0) : 0;
        bool ga = bwd ? (lane - 16 < NT) : (lane < NT);  // group-active
        int base = bwd ? 16 : 0;
        int kmax = bwd ? 254 : 255;

        float texp[NT];
#pragma unroll
        for (int i = 0; i < NT; i++)
            texp[i] = __expf(bwd ? trans[rowi * NT + i] : trans[i * NT + lj]);

        // per-lane em stream: idx(k) = B + k*D
        int B = bwd ? (510 * NT + rowi) : lj;
        int D = bwd ? -NT : NT;

        float state;
        if (bwd) state = ga ? __expf(end_t[rowi]) : 0.f;
        else     state = ga ? __expf(start_t[lj] + em_base[lj]) : 0.f;
        int acc_e = 0;

        float em_cur[8], pe_cur[8], em_nxt[8];
#pragma unroll
        for (int u = 0; u < 8; u++) em_cur[u] = ga ? em_base[B + (1 + u) * D] : -1e30f;
#pragma unroll
        for (int u = 0; u < 8; u++) pe_cur[u] = __expf(em_cur[u]);
#pragma unroll
        for (int u = 0; u < 8; u++) em_nxt[u] = ga ? em_base[B + (9 + u) * D] : -1e30f;

        for (int g = 0; g < 32; ++g) {
            int kb = 1 + (g << 3);
#pragma unroll
            for (int u = 0; u < 8; u++) {
                int k = kb + u;
                float pe_c = pe_cur[u];
                pe_cur[u] = __expf(em_nxt[u]);
                em_nxt[u] = ga ? em_base[B + (k + 16) * D] : -1e30f;

                int lblv = s_lbl[bwd ? (511 - k) : (k + 1)];
                int m = (lblv >= 0) && (k <= kmax);

                float y = bwd ? state * pe_c : state;
                float b0 = __shfl_sync(FULLM, y, base + 0);
                float b1 = __shfl_sync(FULLM, y, base + 1);
                float b2 = __shfl_sync(FULLM, y, base + 2);
                float b3 = __shfl_sync(FULLM, y, base + 3);
                float b4 = __shfl_sync(FULLM, y, base + 4);
                float b5 = __shfl_sync(FULLM, y, base + 5);
                float b6 = __shfl_sync(FULLM, y, base + 6);
                float b7 = __shfl_sync(FULLM, y, base + 7);
                float b8 = __shfl_sync(FULLM, y, base + 8);

                float d0 = fmaf(b6, texp[6], fmaf(b3, texp[3], b0 * texp[0]));
                float d1 = fmaf(b7, texp[7], fmaf(b4, texp[4], b1 * texp[1]));
                float d2 = fmaf(b8, texp[8], fmaf(b5, texp[5], b2 * texp[2]));
                float dt = (d0 + d1) + d2;
                float nv = bwd ? dt : dt * pe_c;
                state = m ? nv : state;
            }
            float ref = __shfl_sync(FULLM, state, base + 4);
            int Eb = (__float_as_int(ref) >> 23) & 0xff;
            int Es = Eb ? Eb : 127;
            state *= __int_as_float((254 - Es) << 23);
            acc_e += Es - 127;
        }

        float bv = __shfl_sync(FULLM, state, (lane & 15) + 16);
        float p = (lane < NT) ? state * bv : 0.f;
        p += __shfl_xor_sync(FULLM, p, 8);
        p += __shfl_xor_sync(FULLM, p, 4);
        p += __shfl_xor_sync(FULLM, p, 2);
        p += __shfl_xor_sync(FULLM, p, 1);
        int e_f = __shfl_sync(FULLM, acc_e, 0);
        int e_b = __shfl_sync(FULLM, acc_e, 16);
        if (lane == 0)
            g_den[b] = __logf(p) + (float)(e_f + e_b) * 0.69314718056f;
    } else if (role == 1) {
        // ================= VITERBI (bitwise-exact) ========================
        float tr[NT];
#pragma unroll
        for (int i = 0; i < NT; i++) tr[i] = trans[i * NT + lj];
        float endv = act ? end_t[lane] : -1e30f;
        float vs = act ? (start_t[lane] + em_base[lane]) : -1e30f;

        float em_r[8];
#pragma unroll
        for (int u = 0; u < 8; u++)
            em_r[u] = act ? em_base[(1 + u) * NT + lane] : 0.f;

        for (int g = 0; g < 64; ++g) {
            int sbase = 1 + (g << 3);
#pragma unroll
            for (int u = 0; u < 8; u++) {
                int s = sbase + u;
                float em_c = em_r[u];
                em_r[u] = act ? em_base[(s + 8) * NT + lane] : 0.f;

                int m = s_lbl[s + 1] >= 0;

                float x0 = __shfl_sync(FULLM, vs, 0) + tr[0];
                float x1 = __shfl_sync(FULLM, vs, 1) + tr[1];
                float x2 = __shfl_sync(FULLM, vs, 2) + tr[2];
                float x3 = __shfl_sync(FULLM, vs, 3) + tr[3];
                float x4 = __shfl_sync(FULLM, vs, 4) + tr[4];
                float x5 = __shfl_sync(FULLM, vs, 5) + tr[5];
                float x6 = __shfl_sync(FULLM, vs, 6) + tr[6];
                float x7 = __shfl_sync(FULLM, vs, 7) + tr[7];
                float x8 = __shfl_sync(FULLM, vs, 8) + tr[8];

                float mA = fmaxf(fmaxf(fmaxf(x0, x1), fmaxf(x2, x3)),
                                 fmaxf(fmaxf(x4, x5), fmaxf(x6, fmaxf(x7, x8))));
                float vn = mA + em_c;
                vs = (m && act) ? vn : vs;

                int bi = 8;
                if (x7 == mA) bi = 7;
                if (x6 == mA) bi = 6;
                if (x5 == mA) bi = 5;
                if (x4 == mA) bi = 4;
                if (x3 == mA) bi = 3;
                if (x2 == mA) bi = 2;
                if (x1 == mA) bi = 1;
                if (x0 == mA) bi = 0;

                if (act)
                    hist[(s - 1) * 12 + lane] = (unsigned char)(m ? bi : lane);
            }
        }

        float fv = vs + endv;
        int fi = act ? lane : 15;
#pragma unroll
        for (int off = 8; off > 0; off >>= 1) {
            float ov = __shfl_xor_sync(FULLM, fv, off);
            int oi = __shfl_xor_sync(FULLM, fi, off);
            bool take = (ov > fv) || (ov == fv && oi < fi);
            fv = take ? ov : fv;
            fi = take ? oi : fi;
        }
        int last = __shfl_sync(FULLM, fi, 0);
        __syncwarp();

        // parallel backtrack: 16-step nibble-packed segment maps
        int a = lane * 16;
        int bnd = a + 16 < (SL - 1) ? a + 16 : (SL - 1);
        unsigned long long F = 0x876543210ull;
        for (int s = bnd - 1; s >= a; --s) {
            const unsigned char* hr = hist + s * 12;
            unsigned long long nF = 0;
#pragma unroll
            for (int t = 0; t < NT; t++) {
                int e = (int)((F >> (4 * t)) & 15);
                nF |= ((unsigned long long)hr[e]) << (4 * t);
            }
            F = nF;
        }
        unsigned int flo = (unsigned int)F, fhi = (unsigned int)(F >> 32);
        int cur = last;
        int my_entry = (lane == 31) ? last : 0;
        for (int l = 31; l >= 1; --l) {
            unsigned int lo = __shfl_sync(FULLM, flo, l);
            unsigned int hi = __shfl_sync(FULLM, fhi, l);
            unsigned long long Fl = ((unsigned long long)hi << 32) | lo;
            cur = (int)((Fl >> (4 * cur)) & 15);
            if (lane == l - 1) my_entry = cur;
        }

        float* otag = out + 1 + (size_t)b * SL;
        if (lane == 31) otag[SL - 1] = (s_lbl[SL] >= 0) ? (float)last : 0.f;
        int c2 = my_entry;
        for (int s = bnd - 1; s >= a; --s) {
            c2 = hist[s * 12 + c2];
            otag[s] = (s_lbl[s + 1] >= 0) ? (float)c2 : 0.f;
        }
    } else {
        // ================= NUMERATOR (order-free parallel sum) =============
        int t0 = lane * 16;
        float sum = 0.f;
        int prev = -1, ftag = -1;
        for (int k = 0; k < 16; ++k) {
            int t = t0 + k;
            if (t == 0 || t > 509) continue;
            int lv = s_lbl[t + 1];
            if (lv >= 0) {
                sum += em_base[t * NT + lv];
                if (prev >= 0) sum += trans[prev * NT + lv];
                else ftag = lv;
                prev = lv;
            }
        }
        int l1 = s_lbl[1];
        int tag0 = (l1 >= 0) ? l1 : 0;

        int x = prev;
#pragma unroll
        for (int off = 1; off < 32; off <<= 1) {
            int y = __shfl_up_sync(FULLM, x, off);
            if (lane >= off && x < 0) x = y;
        }
        int excl = __shfl_up_sync(FULLM, x, 1);
        int carry = (lane == 0 || excl < 0) ? tag0 : excl;

        if (ftag >= 0) sum += trans[carry * NT + ftag];
        if (lane == 0) sum += start_t[tag0] + em_base[tag0];
        if (lane == 31) sum += end_t[(x < 0) ? tag0 : x];

#pragma unroll
        for (int off = 16; off > 0; off >>= 1)
            sum += __shfl_xor_sync(FULLM, sum, off);
        if (lane == 0) g_part[b] = sum;
    }
}

// ---------------------------------------------------------------------------
__global__ __launch_bounds__(64) void reduce_kernel(float* __restrict__ out) {
    int l = threadIdx.x;
    float v = g_part[l] - g_den[l];
#pragma unroll
    for (int o = 16; o > 0; o >>= 1) v += __shfl_xor_sync(FULLM, v, o);
    __shared__ float t2[2];
    if ((l & 31) == 0) t2[l >> 5] = v;
    __syncthreads();
    if (l == 0) out[0] = -(t2[0] + t2[1]);
}

// ---------------------------------------------------------------------------
extern "C" void kernel_launch(void* const* d_in, const int* in_sizes, int n_in,
                              void* d_out, int out_size) {
    const float* hidden  = (const float*)d_in[0];
    const int*   labels  = (const int*)d_in[1];
    const float* weight  = (const float*)d_in[2];
    const float* bias    = (const float*)d_in[3];
    const float* start_t = (const float*)d_in[4];
    const float* end_t   = (const float*)d_in[5];
    const float* trans   = (const float*)d_in[6];
    float* out = (float*)d_out;

    emis_kernel<<<1020, 256>>>(hidden, weight, bias);
    crf_kernel<<<3 * NB, 32>>>(labels, start_t, end_t, trans, out);
    reduce_kernel<<<1, 64>>>(out);
}